// round 14
// baseline (speedup 1.0000x reference)
#include <cuda_runtime.h>
#include <cuda_fp16.h>
#include <mma.h>
#include <math.h>

using namespace nvcuda;

#define H_DIM 64
#define F_IN 128
#define MAXN 100032
#define CAP  128

// scratch
__device__ __half g_xth[(size_t)MAXN * H_DIM];   // fp16 messages, prescaled by dis (in gemm)
__device__ float  g_dis[MAXN];
__device__ int    g_cur[MAXN];
__device__ int    g_src[(size_t)MAXN * CAP];     // padded CSR buckets
__device__ int    g_is64;

typedef unsigned long long ull;

__device__ __forceinline__ ull pk2(float x) {
    ull r; asm("mov.b64 %0, {%1, %1};" : "=l"(r) : "f"(x)); return r;
}
__device__ __forceinline__ void fma2(ull& d, ull a, ull b) {
    asm("fma.rn.f32x2 %0, %1, %2, %0;" : "+l"(d) : "l"(a), "l"(b));
}
__device__ __forceinline__ float2 up2(ull v) {
    float2 f; asm("mov.b64 {%0, %1}, %2;" : "=f"(f.x), "=f"(f.y) : "l"(v)); return f;
}
__device__ __forceinline__ float ftanh(float x) {
    float y; asm("tanh.approx.f32 %0, %1;" : "=f"(y) : "f"(x)); return y;
}
__device__ __forceinline__ float fsigm(float x) {
    return fmaf(0.5f, ftanh(0.5f * x), 0.5f);
}

__device__ __forceinline__ void hadd8(float acc[8], uint4 v) {
    const __half2* h = (const __half2*)&v;
    #pragma unroll
    for (int q = 0; q < 4; q++) {
        float2 f = __half22float2(h[q]);
        acc[2 * q]     += f.x;
        acc[2 * q + 1] += f.y;
    }
}

// ---------------------------------------------------------------------------
__global__ void k_detect(const unsigned int* __restrict__ p) {
    if (threadIdx.x == 0) {
        int is64 = 1;
        for (int i = 0; i < 64; i++)
            if (p[2 * i + 1] != 0u) { is64 = 0; break; }
        g_is64 = is64;
    }
}

__global__ __launch_bounds__(256) void k_zero(int N) {
    int i = blockIdx.x * 256 + threadIdx.x;
    if (i < N) g_cur[i] = 0;
}

// ---------------------------------------------------------------------------
// xt16 = fp16( dis[n] * (x @ W_gcn) ) via HMMA; prescale fused in epilogue.
// Runs AFTER k_dis (launcher reordered).
// ---------------------------------------------------------------------------
__global__ __launch_bounds__(256) void k_gemm_xt(const float* __restrict__ x,
                                                 const float* __restrict__ W,
                                                 int N) {
    extern __shared__ char smb[];
    __half* sA = (__half*)smb;             // [128][136]
    __half* sB = (__half*)(smb + 34816);   // [128][72]
    float*  sC = (float*)smb;              // aliased [128][68]

    const int tid  = threadIdx.x;
    const int base = blockIdx.x * 128;

    for (int i = tid; i < 128 * 32; i += 256) {
        int r = i >> 5, q = i & 31;
        int n = base + r;
        float4 v = make_float4(0.f, 0.f, 0.f, 0.f);
        if (n < N) v = *(const float4*)&x[(long)n * F_IN + q * 4];
        uint2 pk;
        __half2* ph = (__half2*)&pk;
        ph[0] = __float22half2_rn(make_float2(v.x, v.y));
        ph[1] = __float22half2_rn(make_float2(v.z, v.w));
        *(uint2*)&sA[r * 136 + q * 4] = pk;
    }
    for (int i = tid; i < 128 * 16; i += 256) {
        int k = i >> 4, q = i & 15;
        float4 v = *(const float4*)&W[k * H_DIM + q * 4];
        uint2 pk;
        __half2* ph = (__half2*)&pk;
        ph[0] = __float22half2_rn(make_float2(v.x, v.y));
        ph[1] = __float22half2_rn(make_float2(v.z, v.w));
        *(uint2*)&sB[k * 72 + q * 4] = pk;
    }
    __syncthreads();

    const int w = tid >> 5;
    wmma::fragment<wmma::accumulator, 16, 16, 16, float> acc[4];
    #pragma unroll
    for (int ct = 0; ct < 4; ct++) wmma::fill_fragment(acc[ct], 0.0f);

    #pragma unroll
    for (int kk = 0; kk < 8; kk++) {
        wmma::fragment<wmma::matrix_a, 16, 16, 16, __half, wmma::row_major> fa;
        wmma::load_matrix_sync(fa, sA + w * 16 * 136 + kk * 16, 136);
        #pragma unroll
        for (int ct = 0; ct < 4; ct++) {
            wmma::fragment<wmma::matrix_b, 16, 16, 16, __half, wmma::row_major> fb;
            wmma::load_matrix_sync(fb, sB + kk * 16 * 72 + ct * 16, 72);
            wmma::mma_sync(acc[ct], fa, fb, acc[ct]);
        }
    }
    __syncthreads();

    #pragma unroll
    for (int ct = 0; ct < 4; ct++)
        wmma::store_matrix_sync(sC + w * 16 * 68 + ct * 16, acc[ct], 68,
                                wmma::mem_row_major);
    __syncthreads();

    for (int i = tid; i < 128 * 16; i += 256) {
        int r = i >> 4, q = i & 15;
        int n = base + r;
        if (n < N) {
            float d = g_dis[n];
            float4 v = *(const float4*)&sC[r * 68 + q * 4];
            uint2 pk;
            __half2* ph = (__half2*)&pk;
            ph[0] = __float22half2_rn(make_float2(v.x * d, v.y * d));
            ph[1] = __float22half2_rn(make_float2(v.z * d, v.w * d));
            *(uint2*)&g_xth[(long)n * H_DIM + q * 4] = pk;
        }
    }
}

// ---------------------------------------------------------------------------
// Counting-sort scatter (vectorized edge loads).
// ---------------------------------------------------------------------------
__global__ __launch_bounds__(256) void k_scatter(const void* __restrict__ eidx, int E) {
    int i0 = (blockIdx.x * 256 + threadIdx.x) * 4;
    if (i0 >= E) return;
    int m = E - i0; if (m > 4) m = 4;

    int row[4], col[4];
    if (g_is64) {
        const longlong2* pr = (const longlong2*)((const long long*)eidx + i0);
        const long long* pcs = (const long long*)eidx + E + i0;
        if (m == 4 && (((size_t)pcs) & 15) == 0) {
            longlong2 r01 = pr[0], r23 = pr[1];
            longlong2 c01 = ((const longlong2*)pcs)[0], c23 = ((const longlong2*)pcs)[1];
            row[0] = (int)r01.x; row[1] = (int)r01.y; row[2] = (int)r23.x; row[3] = (int)r23.y;
            col[0] = (int)c01.x; col[1] = (int)c01.y; col[2] = (int)c23.x; col[3] = (int)c23.y;
        } else {
            const long long* p = (const long long*)eidx;
            #pragma unroll
            for (int q = 0; q < 4; q++)
                if (q < m) { row[q] = (int)p[i0 + q]; col[q] = (int)p[(long)E + i0 + q]; }
        }
    } else {
        const int* p = (const int*)eidx;
        if (m == 4 && ((E + i0) & 3) == 0) {
            int4 r4 = *(const int4*)&p[i0];
            int4 c4 = *(const int4*)&p[E + i0];
            row[0] = r4.x; row[1] = r4.y; row[2] = r4.z; row[3] = r4.w;
            col[0] = c4.x; col[1] = c4.y; col[2] = c4.z; col[3] = c4.w;
        } else {
            #pragma unroll
            for (int q = 0; q < 4; q++)
                if (q < m) { row[q] = p[i0 + q]; col[q] = p[E + i0 + q]; }
        }
    }
    int pos[4];
    #pragma unroll
    for (int q = 0; q < 4; q++)
        if (q < m) pos[q] = atomicAdd(&g_cur[col[q]], 1);
    #pragma unroll
    for (int q = 0; q < 4; q++)
        if (q < m && pos[q] < CAP) g_src[(long)col[q] * CAP + pos[q]] = row[q];
}

__global__ __launch_bounds__(256) void k_dis(int N) {
    int i = blockIdx.x * 256 + threadIdx.x;
    if (i < N) g_dis[i] = rsqrtf((float)(g_cur[i] + 1));
}

// ---------------------------------------------------------------------------
// Gather (prescaled fp16 messages, fp32 accum): 8 threads/node, 16B each.
// 8-wide unrolled main loop (MLP=8), 4-wide step, scalar tail.
//   out[n] = dis[n] * ( xt'[n] + sum_src xt'[src] )
// ---------------------------------------------------------------------------
__global__ __launch_bounds__(256) void k_gather(float* __restrict__ out, int N) {
    const int tid = threadIdx.x;
    const int nl  = tid >> 3, c = tid & 7;
    const int n   = blockIdx.x * 32 + nl;
    if (n >= N) return;

    int cnt = g_cur[n];
    if (cnt > CAP) cnt = CAP;
    const long b = (long)n * CAP;
    const long co = (long)c * 8;

    float acc[8] = {0.f};
    hadd8(acc, __ldcg((const uint4*)&g_xth[(long)n * H_DIM + co]));  // self loop

    int e = 0;
    for (; e + 8 <= cnt; e += 8) {
        int4 s0 = *(const int4*)&g_src[b + e];
        int4 s1 = *(const int4*)&g_src[b + e + 4];
        uint4 v0 = __ldcg((const uint4*)&g_xth[(long)s0.x * H_DIM + co]);
        uint4 v1 = __ldcg((const uint4*)&g_xth[(long)s0.y * H_DIM + co]);
        uint4 v2 = __ldcg((const uint4*)&g_xth[(long)s0.z * H_DIM + co]);
        uint4 v3 = __ldcg((const uint4*)&g_xth[(long)s0.w * H_DIM + co]);
        uint4 v4 = __ldcg((const uint4*)&g_xth[(long)s1.x * H_DIM + co]);
        uint4 v5 = __ldcg((const uint4*)&g_xth[(long)s1.y * H_DIM + co]);
        uint4 v6 = __ldcg((const uint4*)&g_xth[(long)s1.z * H_DIM + co]);
        uint4 v7 = __ldcg((const uint4*)&g_xth[(long)s1.w * H_DIM + co]);
        hadd8(acc, v0); hadd8(acc, v1); hadd8(acc, v2); hadd8(acc, v3);
        hadd8(acc, v4); hadd8(acc, v5); hadd8(acc, v6); hadd8(acc, v7);
    }
    for (; e + 4 <= cnt; e += 4) {
        int4 s = *(const int4*)&g_src[b + e];
        uint4 v0 = __ldcg((const uint4*)&g_xth[(long)s.x * H_DIM + co]);
        uint4 v1 = __ldcg((const uint4*)&g_xth[(long)s.y * H_DIM + co]);
        uint4 v2 = __ldcg((const uint4*)&g_xth[(long)s.z * H_DIM + co]);
        uint4 v3 = __ldcg((const uint4*)&g_xth[(long)s.w * H_DIM + co]);
        hadd8(acc, v0); hadd8(acc, v1); hadd8(acc, v2); hadd8(acc, v3);
    }
    for (; e < cnt; e++) {
        int r = g_src[b + e];
        hadd8(acc, __ldcg((const uint4*)&g_xth[(long)r * H_DIM + co]));
    }

    const float dn = g_dis[n];
    float4 o0 = make_float4(acc[0] * dn, acc[1] * dn, acc[2] * dn, acc[3] * dn);
    float4 o1 = make_float4(acc[4] * dn, acc[5] * dn, acc[6] * dn, acc[7] * dn);
    *(float4*)&out[(long)n * H_DIM + co]     = o0;
    *(float4*)&out[(long)n * H_DIM + co + 4] = o1;
}

// ---------------------------------------------------------------------------
// Fused GRU (R9 version): 128 nodes/block, TWO-PASS, packed f32x2 FMA,
// tanh.approx activations.
// ---------------------------------------------------------------------------
__global__ __launch_bounds__(256, 1) void k_gru(float* __restrict__ out,
                                                const float* __restrict__ h0,
                                                const float* __restrict__ Wih,
                                                const float* __restrict__ Whh,
                                                const float* __restrict__ bih,
                                                const float* __restrict__ bhh,
                                                const float* __restrict__ bg,
                                                int N, int NH, int dup) {
    extern __shared__ float sm[];
    float* gs = sm;                    // 64*132
    float* hs = gs + 64 * 132;
    float* wi = hs + 64 * 132;         // 64*196
    float* wh = wi + 64 * 196;

    const int tid  = threadIdx.x;
    const int base = blockIdx.x * 128;

    for (int i = tid; i < 128 * 64; i += 256) {
        int nl = i >> 6, c = i & 63;
        int n = base + nl;
        float gv = 0.0f, hv = 0.0f;
        if (n < N) {
            gv = out[(long)n * H_DIM + c] + bg[c];
            gv = fmaxf(gv, 0.0f);
            hv = h0[(long)n * H_DIM + c];
        }
        gs[c * 132 + nl] = gv;
        hs[c * 132 + nl] = hv;
    }
    for (int i = tid; i < 192 * 64; i += 256) {
        int j = i >> 6, k = i & 63;
        wi[k * 196 + j] = Wih[i];
        wh[k * 196 + j] = Whh[i];
    }
    __syncthreads();

    const int ty = tid >> 4, tx = tid & 15;
    const int r0 = ty * 8, c0 = tx * 4;
    const ull z0 = pk2(0.0f);

    float rv[8][4], zv[8][4];

    // ---- pass 1: gates r and z ----
    {
        ull R[4][4], Z[4][4];
        #pragma unroll
        for (int ip = 0; ip < 4; ip++)
            #pragma unroll
            for (int j = 0; j < 4; j++) { R[ip][j] = z0; Z[ip][j] = z0; }

        #pragma unroll 2
        for (int k = 0; k < H_DIM; k++) {
            ulonglong2 a01 = *(const ulonglong2*)&gs[k * 132 + r0];
            ulonglong2 a23 = *(const ulonglong2*)&gs[k * 132 + r0 + 4];
            ulonglong2 h01 = *(const ulonglong2*)&hs[k * 132 + r0];
            ulonglong2 h23 = *(const ulonglong2*)&hs[k * 132 + r0 + 4];
            ull ap[4] = {a01.x, a01.y, a23.x, a23.y};
            ull hp[4] = {h01.x, h01.y, h23.x, h23.y};

            float4 ur = *(const float4*)&wi[k * 196 + c0];
            float4 vr = *(const float4*)&wh[k * 196 + c0];
            float4 uz = *(const float4*)&wi[k * 196 + 64 + c0];
            float4 vz = *(const float4*)&wh[k * 196 + 64 + c0];
            ull urb[4] = {pk2(ur.x), pk2(ur.y), pk2(ur.z), pk2(ur.w)};
            ull vrb[4] = {pk2(vr.x), pk2(vr.y), pk2(vr.z), pk2(vr.w)};
            ull uzb[4] = {pk2(uz.x), pk2(uz.y), pk2(uz.z), pk2(uz.w)};
            ull vzb[4] = {pk2(vz.x), pk2(vz.y), pk2(vz.z), pk2(vz.w)};

            #pragma unroll
            for (int ip = 0; ip < 4; ip++)
                #pragma unroll
                for (int j = 0; j < 4; j++) {
                    fma2(R[ip][j], ap[ip], urb[j]);
                    fma2(R[ip][j], hp[ip], vrb[j]);
                    fma2(Z[ip][j], ap[ip], uzb[j]);
                    fma2(Z[ip][j], hp[ip], vzb[j]);
                }
        }

        float4 b1r = *(const float4*)&bih[c0];
        float4 b2r = *(const float4*)&bhh[c0];
        float4 b1z = *(const float4*)&bih[64 + c0];
        float4 b2z = *(const float4*)&bhh[64 + c0];
        float br[4] = {b1r.x + b2r.x, b1r.y + b2r.y, b1r.z + b2r.z, b1r.w + b2r.w};
        float bz[4] = {b1z.x + b2z.x, b1z.y + b2z.y, b1z.z + b2z.z, b1z.w + b2z.w};

        #pragma unroll
        for (int ip = 0; ip < 4; ip++)
            #pragma unroll
            for (int j = 0; j < 4; j++) {
                float2 rr = up2(R[ip][j]);
                float2 zz = up2(Z[ip][j]);
                rv[2 * ip][j]     = fsigm(rr.x + br[j]);
                rv[2 * ip + 1][j] = fsigm(rr.y + br[j]);
                zv[2 * ip][j]     = fsigm(zz.x + bz[j]);
                zv[2 * ip + 1][j] = fsigm(zz.y + bz[j]);
            }
    }

    // ---- pass 2: gate n + output ----
    {
        ull NA[4][4], NB[4][4];
        #pragma unroll
        for (int ip = 0; ip < 4; ip++)
            #pragma unroll
            for (int j = 0; j < 4; j++) { NA[ip][j] = z0; NB[ip][j] = z0; }

        #pragma unroll 2
        for (int k = 0; k < H_DIM; k++) {
            ulonglong2 a01 = *(const ulonglong2*)&gs[k * 132 + r0];
            ulonglong2 a23 = *(const ulonglong2*)&gs[k * 132 + r0 + 4];
            ulonglong2 h01 = *(const ulonglong2*)&hs[k * 132 + r0];
            ulonglong2 h23 = *(const ulonglong2*)&hs[k * 132 + r0 + 4];
            ull ap[4] = {a01.x, a01.y, a23.x, a23.y};
            ull hp[4] = {h01.x, h01.y, h23.x, h23.y};

            float4 un = *(const float4*)&wi[k * 196 + 128 + c0];
            float4 vn = *(const float4*)&wh[k * 196 + 128 + c0];
            ull unb[4] = {pk2(un.x), pk2(un.y), pk2(un.z), pk2(un.w)};
            ull vnb[4] = {pk2(vn.x), pk2(vn.y), pk2(vn.z), pk2(vn.w)};

            #pragma unroll
            for (int ip = 0; ip < 4; ip++)
                #pragma unroll
                for (int j = 0; j < 4; j++) {
                    fma2(NA[ip][j], ap[ip], unb[j]);
                    fma2(NB[ip][j], hp[ip], vnb[j]);
                }
        }

        float4 b1n = *(const float4*)&bih[128 + c0];
        float4 b2n = *(const float4*)&bhh[128 + c0];
        float bi[4] = {b1n.x, b1n.y, b1n.z, b1n.w};
        float bh[4] = {b2n.x, b2n.y, b2n.z, b2n.w};

        float ov[8][4];
        #pragma unroll
        for (int ip = 0; ip < 4; ip++)
            #pragma unroll
            for (int j = 0; j < 4; j++) {
                float2 na = up2(NA[ip][j]);
                float2 nb = up2(NB[ip][j]);
                float2 hv = *(const float2*)&hs[(c0 + j) * 132 + r0 + 2 * ip];
                int i0 = 2 * ip;
                float n0f = ftanh(na.x + bi[j] + rv[i0][j] * (nb.x + bh[j]));
                float n1f = ftanh(na.y + bi[j] + rv[i0 + 1][j] * (nb.y + bh[j]));
                ov[i0][j]     = (1.0f - zv[i0][j]) * n0f + zv[i0][j] * hv.x;
                ov[i0 + 1][j] = (1.0f - zv[i0 + 1][j]) * n1f + zv[i0 + 1][j] * hv.y;
            }

        #pragma unroll
        for (int i = 0; i < 8; i++) {
            int n = base + r0 + i;
            if (n < N) {
                float4 o = make_float4(ov[i][0], ov[i][1], ov[i][2], ov[i][3]);
                *(float4*)&out[(long)n * H_DIM + c0] = o;
                if (dup) *(float4*)&out[(long)NH + (long)n * H_DIM + c0] = o;
            }
        }
    }
}

// ---------------------------------------------------------------------------
extern "C" void kernel_launch(void* const* d_in, const int* in_sizes, int n_in,
                              void* d_out, int out_size) {
    const float* x    = (const float*)d_in[0];
    const void*  eidx = d_in[1];
    const float* h0   = (const float*)d_in[2];
    const float* Wg   = (const float*)d_in[3];
    const float* bg   = (const float*)d_in[4];
    const float* Wih  = (const float*)d_in[5];
    const float* Whh  = (const float*)d_in[6];
    const float* bih  = (const float*)d_in[7];
    const float* bhh  = (const float*)d_in[8];
    float* out = (float*)d_out;

    const int  N  = in_sizes[0] / F_IN;
    const int  E  = in_sizes[1] / 2;
    const long NH = (long)N * H_DIM;
    const int  dup = (out_size >= 2 * NH) ? 1 : 0;

    k_detect<<<1, 32>>>((const unsigned int*)eidx);
    k_zero<<<(N + 255) / 256, 256>>>(N);
    k_scatter<<<(E / 4 + 255) / 256, 256>>>(eidx, E);
    k_dis<<<(N + 255) / 256, 256>>>(N);

    const int gemm_smem = 53248;
    cudaFuncSetAttribute(k_gemm_xt, cudaFuncAttributeMaxDynamicSharedMemorySize, gemm_smem);
    k_gemm_xt<<<(N + 127) / 128, 256, gemm_smem>>>(x, Wg, N);

    k_gather<<<(N + 31) / 32, 256>>>(out, N);

    const int gru_smem = (2 * 64 * 132 + 2 * 64 * 196) * (int)sizeof(float);
    cudaFuncSetAttribute(k_gru, cudaFuncAttributeMaxDynamicSharedMemorySize, gru_smem);
    k_gru<<<(N + 127) / 128, 256, gru_smem>>>(out, h0, Wih, Whh, bih, bhh, bg,
                                              N, (int)NH, dup);
}

// round 15
// speedup vs baseline: 1.0060x; 1.0060x over previous
#include <cuda_runtime.h>
#include <cuda_fp16.h>
#include <mma.h>
#include <math.h>

using namespace nvcuda;

#define H_DIM 64
#define F_IN 128
#define MAXN 100032
#define CAP  128

// scratch
__device__ __half g_xth[(size_t)MAXN * H_DIM];   // fp16 messages, prescaled by dis (in gemm)
__device__ float  g_dis[MAXN];
__device__ int    g_cur[MAXN];
__device__ int    g_src[(size_t)MAXN * CAP];     // padded CSR buckets
__device__ int    g_is64;

typedef unsigned long long ull;

__device__ __forceinline__ ull pk2(float x) {
    ull r; asm("mov.b64 %0, {%1, %1};" : "=l"(r) : "f"(x)); return r;
}
__device__ __forceinline__ void fma2(ull& d, ull a, ull b) {
    asm("fma.rn.f32x2 %0, %1, %2, %0;" : "+l"(d) : "l"(a), "l"(b));
}
__device__ __forceinline__ float2 up2(ull v) {
    float2 f; asm("mov.b64 {%0, %1}, %2;" : "=f"(f.x), "=f"(f.y) : "l"(v)); return f;
}
__device__ __forceinline__ float ftanh(float x) {
    float y; asm("tanh.approx.f32 %0, %1;" : "=f"(y) : "f"(x)); return y;
}
__device__ __forceinline__ float fsigm(float x) {
    return fmaf(0.5f, ftanh(0.5f * x), 0.5f);
}

__device__ __forceinline__ void hadd8(float acc[8], uint4 v) {
    const __half2* h = (const __half2*)&v;
    #pragma unroll
    for (int q = 0; q < 4; q++) {
        float2 f = __half22float2(h[q]);
        acc[2 * q]     += f.x;
        acc[2 * q + 1] += f.y;
    }
}

// ---------------------------------------------------------------------------
__global__ void k_detect(const unsigned int* __restrict__ p) {
    if (threadIdx.x == 0) {
        int is64 = 1;
        for (int i = 0; i < 64; i++)
            if (p[2 * i + 1] != 0u) { is64 = 0; break; }
        g_is64 = is64;
    }
}

__global__ __launch_bounds__(256) void k_zero(int N) {
    int i = blockIdx.x * 256 + threadIdx.x;
    if (i < N) g_cur[i] = 0;
}

// ---------------------------------------------------------------------------
// xt16 = fp16( dis[n] * (x @ W_gcn) ) via HMMA; prescale fused in epilogue.
// Runs AFTER k_dis.
// ---------------------------------------------------------------------------
__global__ __launch_bounds__(256) void k_gemm_xt(const float* __restrict__ x,
                                                 const float* __restrict__ W,
                                                 int N) {
    extern __shared__ char smb[];
    __half* sA = (__half*)smb;             // [128][136]
    __half* sB = (__half*)(smb + 34816);   // [128][72]
    float*  sC = (float*)smb;              // aliased [128][68]

    const int tid  = threadIdx.x;
    const int base = blockIdx.x * 128;

    for (int i = tid; i < 128 * 32; i += 256) {
        int r = i >> 5, q = i & 31;
        int n = base + r;
        float4 v = make_float4(0.f, 0.f, 0.f, 0.f);
        if (n < N) v = *(const float4*)&x[(long)n * F_IN + q * 4];
        uint2 pk;
        __half2* ph = (__half2*)&pk;
        ph[0] = __float22half2_rn(make_float2(v.x, v.y));
        ph[1] = __float22half2_rn(make_float2(v.z, v.w));
        *(uint2*)&sA[r * 136 + q * 4] = pk;
    }
    for (int i = tid; i < 128 * 16; i += 256) {
        int k = i >> 4, q = i & 15;
        float4 v = *(const float4*)&W[k * H_DIM + q * 4];
        uint2 pk;
        __half2* ph = (__half2*)&pk;
        ph[0] = __float22half2_rn(make_float2(v.x, v.y));
        ph[1] = __float22half2_rn(make_float2(v.z, v.w));
        *(uint2*)&sB[k * 72 + q * 4] = pk;
    }
    __syncthreads();

    const int w = tid >> 5;
    wmma::fragment<wmma::accumulator, 16, 16, 16, float> acc[4];
    #pragma unroll
    for (int ct = 0; ct < 4; ct++) wmma::fill_fragment(acc[ct], 0.0f);

    #pragma unroll
    for (int kk = 0; kk < 8; kk++) {
        wmma::fragment<wmma::matrix_a, 16, 16, 16, __half, wmma::row_major> fa;
        wmma::load_matrix_sync(fa, sA + w * 16 * 136 + kk * 16, 136);
        #pragma unroll
        for (int ct = 0; ct < 4; ct++) {
            wmma::fragment<wmma::matrix_b, 16, 16, 16, __half, wmma::row_major> fb;
            wmma::load_matrix_sync(fb, sB + kk * 16 * 72 + ct * 16, 72);
            wmma::mma_sync(acc[ct], fa, fb, acc[ct]);
        }
    }
    __syncthreads();

    #pragma unroll
    for (int ct = 0; ct < 4; ct++)
        wmma::store_matrix_sync(sC + w * 16 * 68 + ct * 16, acc[ct], 68,
                                wmma::mem_row_major);
    __syncthreads();

    for (int i = tid; i < 128 * 16; i += 256) {
        int r = i >> 4, q = i & 15;
        int n = base + r;
        if (n < N) {
            float d = g_dis[n];
            float4 v = *(const float4*)&sC[r * 68 + q * 4];
            uint2 pk;
            __half2* ph = (__half2*)&pk;
            ph[0] = __float22half2_rn(make_float2(v.x * d, v.y * d));
            ph[1] = __float22half2_rn(make_float2(v.z * d, v.w * d));
            *(uint2*)&g_xth[(long)n * H_DIM + q * 4] = pk;
        }
    }
}

// ---------------------------------------------------------------------------
// Counting-sort scatter (vectorized edge loads).
// ---------------------------------------------------------------------------
__global__ __launch_bounds__(256) void k_scatter(const void* __restrict__ eidx, int E) {
    int i0 = (blockIdx.x * 256 + threadIdx.x) * 4;
    if (i0 >= E) return;
    int m = E - i0; if (m > 4) m = 4;

    int row[4], col[4];
    if (g_is64) {
        const longlong2* pr = (const longlong2*)((const long long*)eidx + i0);
        const long long* pcs = (const long long*)eidx + E + i0;
        if (m == 4 && (((size_t)pcs) & 15) == 0) {
            longlong2 r01 = pr[0], r23 = pr[1];
            longlong2 c01 = ((const longlong2*)pcs)[0], c23 = ((const longlong2*)pcs)[1];
            row[0] = (int)r01.x; row[1] = (int)r01.y; row[2] = (int)r23.x; row[3] = (int)r23.y;
            col[0] = (int)c01.x; col[1] = (int)c01.y; col[2] = (int)c23.x; col[3] = (int)c23.y;
        } else {
            const long long* p = (const long long*)eidx;
            #pragma unroll
            for (int q = 0; q < 4; q++)
                if (q < m) { row[q] = (int)p[i0 + q]; col[q] = (int)p[(long)E + i0 + q]; }
        }
    } else {
        const int* p = (const int*)eidx;
        if (m == 4 && ((E + i0) & 3) == 0) {
            int4 r4 = *(const int4*)&p[i0];
            int4 c4 = *(const int4*)&p[E + i0];
            row[0] = r4.x; row[1] = r4.y; row[2] = r4.z; row[3] = r4.w;
            col[0] = c4.x; col[1] = c4.y; col[2] = c4.z; col[3] = c4.w;
        } else {
            #pragma unroll
            for (int q = 0; q < 4; q++)
                if (q < m) { row[q] = p[i0 + q]; col[q] = p[E + i0 + q]; }
        }
    }
    int pos[4];
    #pragma unroll
    for (int q = 0; q < 4; q++)
        if (q < m) pos[q] = atomicAdd(&g_cur[col[q]], 1);
    #pragma unroll
    for (int q = 0; q < 4; q++)
        if (q < m && pos[q] < CAP) g_src[(long)col[q] * CAP + pos[q]] = row[q];
}

__global__ __launch_bounds__(256) void k_dis(int N) {
    int i = blockIdx.x * 256 + threadIdx.x;
    if (i < N) g_dis[i] = rsqrtf((float)(g_cur[i] + 1));
}

// ---------------------------------------------------------------------------
// Gather (prescaled fp16 messages, fp32 accum): 8 threads/node, 16B each.
// R13-proven 4-wide loop.
//   out[n] = dis[n] * ( xt'[n] + sum_src xt'[src] )
// ---------------------------------------------------------------------------
__global__ __launch_bounds__(256) void k_gather(float* __restrict__ out, int N) {
    const int tid = threadIdx.x;
    const int nl  = tid >> 3, c = tid & 7;
    const int n   = blockIdx.x * 32 + nl;
    if (n >= N) return;

    int cnt = g_cur[n];
    if (cnt > CAP) cnt = CAP;
    const long b = (long)n * CAP;
    const long co = (long)c * 8;

    float acc[8] = {0.f};
    hadd8(acc, __ldcg((const uint4*)&g_xth[(long)n * H_DIM + co]));  // self loop

    int e = 0;
    for (; e + 4 <= cnt; e += 4) {
        int4 s = *(const int4*)&g_src[b + e];
        uint4 v0 = __ldcg((const uint4*)&g_xth[(long)s.x * H_DIM + co]);
        uint4 v1 = __ldcg((const uint4*)&g_xth[(long)s.y * H_DIM + co]);
        uint4 v2 = __ldcg((const uint4*)&g_xth[(long)s.z * H_DIM + co]);
        uint4 v3 = __ldcg((const uint4*)&g_xth[(long)s.w * H_DIM + co]);
        hadd8(acc, v0); hadd8(acc, v1); hadd8(acc, v2); hadd8(acc, v3);
    }
    for (; e < cnt; e++) {
        int r = g_src[b + e];
        hadd8(acc, __ldcg((const uint4*)&g_xth[(long)r * H_DIM + co]));
    }

    const float dn = g_dis[n];
    float4 o0 = make_float4(acc[0] * dn, acc[1] * dn, acc[2] * dn, acc[3] * dn);
    float4 o1 = make_float4(acc[4] * dn, acc[5] * dn, acc[6] * dn, acc[7] * dn);
    *(float4*)&out[(long)n * H_DIM + co]     = o0;
    *(float4*)&out[(long)n * H_DIM + co + 4] = o1;
}

// ---------------------------------------------------------------------------
// Fused GRU (R9 version): 128 nodes/block, TWO-PASS, packed f32x2 FMA,
// tanh.approx activations.
// ---------------------------------------------------------------------------
__global__ __launch_bounds__(256, 1) void k_gru(float* __restrict__ out,
                                                const float* __restrict__ h0,
                                                const float* __restrict__ Wih,
                                                const float* __restrict__ Whh,
                                                const float* __restrict__ bih,
                                                const float* __restrict__ bhh,
                                                const float* __restrict__ bg,
                                                int N, int NH, int dup) {
    extern __shared__ float sm[];
    float* gs = sm;                    // 64*132
    float* hs = gs + 64 * 132;
    float* wi = hs + 64 * 132;         // 64*196
    float* wh = wi + 64 * 196;

    const int tid  = threadIdx.x;
    const int base = blockIdx.x * 128;

    for (int i = tid; i < 128 * 64; i += 256) {
        int nl = i >> 6, c = i & 63;
        int n = base + nl;
        float gv = 0.0f, hv = 0.0f;
        if (n < N) {
            gv = out[(long)n * H_DIM + c] + bg[c];
            gv = fmaxf(gv, 0.0f);
            hv = h0[(long)n * H_DIM + c];
        }
        gs[c * 132 + nl] = gv;
        hs[c * 132 + nl] = hv;
    }
    for (int i = tid; i < 192 * 64; i += 256) {
        int j = i >> 6, k = i & 63;
        wi[k * 196 + j] = Wih[i];
        wh[k * 196 + j] = Whh[i];
    }
    __syncthreads();

    const int ty = tid >> 4, tx = tid & 15;
    const int r0 = ty * 8, c0 = tx * 4;
    const ull z0 = pk2(0.0f);

    float rv[8][4], zv[8][4];

    // ---- pass 1: gates r and z ----
    {
        ull R[4][4], Z[4][4];
        #pragma unroll
        for (int ip = 0; ip < 4; ip++)
            #pragma unroll
            for (int j = 0; j < 4; j++) { R[ip][j] = z0; Z[ip][j] = z0; }

        #pragma unroll 2
        for (int k = 0; k < H_DIM; k++) {
            ulonglong2 a01 = *(const ulonglong2*)&gs[k * 132 + r0];
            ulonglong2 a23 = *(const ulonglong2*)&gs[k * 132 + r0 + 4];
            ulonglong2 h01 = *(const ulonglong2*)&hs[k * 132 + r0];
            ulonglong2 h23 = *(const ulonglong2*)&hs[k * 132 + r0 + 4];
            ull ap[4] = {a01.x, a01.y, a23.x, a23.y};
            ull hp[4] = {h01.x, h01.y, h23.x, h23.y};

            float4 ur = *(const float4*)&wi[k * 196 + c0];
            float4 vr = *(const float4*)&wh[k * 196 + c0];
            float4 uz = *(const float4*)&wi[k * 196 + 64 + c0];
            float4 vz = *(const float4*)&wh[k * 196 + 64 + c0];
            ull urb[4] = {pk2(ur.x), pk2(ur.y), pk2(ur.z), pk2(ur.w)};
            ull vrb[4] = {pk2(vr.x), pk2(vr.y), pk2(vr.z), pk2(vr.w)};
            ull uzb[4] = {pk2(uz.x), pk2(uz.y), pk2(uz.z), pk2(uz.w)};
            ull vzb[4] = {pk2(vz.x), pk2(vz.y), pk2(vz.z), pk2(vz.w)};

            #pragma unroll
            for (int ip = 0; ip < 4; ip++)
                #pragma unroll
                for (int j = 0; j < 4; j++) {
                    fma2(R[ip][j], ap[ip], urb[j]);
                    fma2(R[ip][j], hp[ip], vrb[j]);
                    fma2(Z[ip][j], ap[ip], uzb[j]);
                    fma2(Z[ip][j], hp[ip], vzb[j]);
                }
        }

        float4 b1r = *(const float4*)&bih[c0];
        float4 b2r = *(const float4*)&bhh[c0];
        float4 b1z = *(const float4*)&bih[64 + c0];
        float4 b2z = *(const float4*)&bhh[64 + c0];
        float br[4] = {b1r.x + b2r.x, b1r.y + b2r.y, b1r.z + b2r.z, b1r.w + b2r.w};
        float bz[4] = {b1z.x + b2z.x, b1z.y + b2z.y, b1z.z + b2z.z, b1z.w + b2z.w};

        #pragma unroll
        for (int ip = 0; ip < 4; ip++)
            #pragma unroll
            for (int j = 0; j < 4; j++) {
                float2 rr = up2(R[ip][j]);
                float2 zz = up2(Z[ip][j]);
                rv[2 * ip][j]     = fsigm(rr.x + br[j]);
                rv[2 * ip + 1][j] = fsigm(rr.y + br[j]);
                zv[2 * ip][j]     = fsigm(zz.x + bz[j]);
                zv[2 * ip + 1][j] = fsigm(zz.y + bz[j]);
            }
    }

    // ---- pass 2: gate n + output ----
    {
        ull NA[4][4], NB[4][4];
        #pragma unroll
        for (int ip = 0; ip < 4; ip++)
            #pragma unroll
            for (int j = 0; j < 4; j++) { NA[ip][j] = z0; NB[ip][j] = z0; }

        #pragma unroll 2
        for (int k = 0; k < H_DIM; k++) {
            ulonglong2 a01 = *(const ulonglong2*)&gs[k * 132 + r0];
            ulonglong2 a23 = *(const ulonglong2*)&gs[k * 132 + r0 + 4];
            ulonglong2 h01 = *(const ulonglong2*)&hs[k * 132 + r0];
            ulonglong2 h23 = *(const ulonglong2*)&hs[k * 132 + r0 + 4];
            ull ap[4] = {a01.x, a01.y, a23.x, a23.y};
            ull hp[4] = {h01.x, h01.y, h23.x, h23.y};

            float4 un = *(const float4*)&wi[k * 196 + 128 + c0];
            float4 vn = *(const float4*)&wh[k * 196 + 128 + c0];
            ull unb[4] = {pk2(un.x), pk2(un.y), pk2(un.z), pk2(un.w)};
            ull vnb[4] = {pk2(vn.x), pk2(vn.y), pk2(vn.z), pk2(vn.w)};

            #pragma unroll
            for (int ip = 0; ip < 4; ip++)
                #pragma unroll
                for (int j = 0; j < 4; j++) {
                    fma2(NA[ip][j], ap[ip], unb[j]);
                    fma2(NB[ip][j], hp[ip], vnb[j]);
                }
        }

        float4 b1n = *(const float4*)&bih[128 + c0];
        float4 b2n = *(const float4*)&bhh[128 + c0];
        float bi[4] = {b1n.x, b1n.y, b1n.z, b1n.w};
        float bh[4] = {b2n.x, b2n.y, b2n.z, b2n.w};

        float ov[8][4];
        #pragma unroll
        for (int ip = 0; ip < 4; ip++)
            #pragma unroll
            for (int j = 0; j < 4; j++) {
                float2 na = up2(NA[ip][j]);
                float2 nb = up2(NB[ip][j]);
                float2 hv = *(const float2*)&hs[(c0 + j) * 132 + r0 + 2 * ip];
                int i0 = 2 * ip;
                float n0f = ftanh(na.x + bi[j] + rv[i0][j] * (nb.x + bh[j]));
                float n1f = ftanh(na.y + bi[j] + rv[i0 + 1][j] * (nb.y + bh[j]));
                ov[i0][j]     = (1.0f - zv[i0][j]) * n0f + zv[i0][j] * hv.x;
                ov[i0 + 1][j] = (1.0f - zv[i0 + 1][j]) * n1f + zv[i0 + 1][j] * hv.y;
            }

        #pragma unroll
        for (int i = 0; i < 8; i++) {
            int n = base + r0 + i;
            if (n < N) {
                float4 o = make_float4(ov[i][0], ov[i][1], ov[i][2], ov[i][3]);
                *(float4*)&out[(long)n * H_DIM + c0] = o;
                if (dup) *(float4*)&out[(long)NH + (long)n * H_DIM + c0] = o;
            }
        }
    }
}

// ---------------------------------------------------------------------------
extern "C" void kernel_launch(void* const* d_in, const int* in_sizes, int n_in,
                              void* d_out, int out_size) {
    const float* x    = (const float*)d_in[0];
    const void*  eidx = d_in[1];
    const float* h0   = (const float*)d_in[2];
    const float* Wg   = (const float*)d_in[3];
    const float* bg   = (const float*)d_in[4];
    const float* Wih  = (const float*)d_in[5];
    const float* Whh  = (const float*)d_in[6];
    const float* bih  = (const float*)d_in[7];
    const float* bhh  = (const float*)d_in[8];
    float* out = (float*)d_out;

    const int  N  = in_sizes[0] / F_IN;
    const int  E  = in_sizes[1] / 2;
    const long NH = (long)N * H_DIM;
    const int  dup = (out_size >= 2 * NH) ? 1 : 0;

    k_detect<<<1, 32>>>((const unsigned int*)eidx);
    k_zero<<<(N + 255) / 256, 256>>>(N);
    k_scatter<<<(E / 4 + 255) / 256, 256>>>(eidx, E);
    k_dis<<<(N + 255) / 256, 256>>>(N);

    const int gemm_smem = 53248;
    cudaFuncSetAttribute(k_gemm_xt, cudaFuncAttributeMaxDynamicSharedMemorySize, gemm_smem);
    k_gemm_xt<<<(N + 127) / 128, 256, gemm_smem>>>(x, Wg, N);

    k_gather<<<(N + 31) / 32, 256>>>(out, N);

    const int gru_smem = (2 * 64 * 132 + 2 * 64 * 196) * (int)sizeof(float);
    cudaFuncSetAttribute(k_gru, cudaFuncAttributeMaxDynamicSharedMemorySize, gru_smem);
    k_gru<<<(N + 127) / 128, 256, gru_smem>>>(out, h0, Wih, Whh, bih, bhh, bg,
                                              N, (int)NH, dup);
}

// round 16
// speedup vs baseline: 1.0235x; 1.0174x over previous
#include <cuda_runtime.h>
#include <cuda_fp16.h>
#include <mma.h>
#include <math.h>

using namespace nvcuda;

#define H_DIM 64
#define F_IN 128
#define MAXN 100032
#define CAP  128

// scratch (g_cur is zero at load; every run leaves it zero via k_gru epilogue)
__device__ __half g_xth[(size_t)MAXN * H_DIM];   // fp16 messages; prescaled by dis in k_scale
__device__ float  g_dis[MAXN];
__device__ int    g_cur[MAXN];
__device__ int    g_src[(size_t)MAXN * CAP];     // padded CSR buckets
__device__ int    g_is64;

typedef unsigned long long ull;

__device__ __forceinline__ ull pk2(float x) {
    ull r; asm("mov.b64 %0, {%1, %1};" : "=l"(r) : "f"(x)); return r;
}
__device__ __forceinline__ void fma2(ull& d, ull a, ull b) {
    asm("fma.rn.f32x2 %0, %1, %2, %0;" : "+l"(d) : "l"(a), "l"(b));
}
__device__ __forceinline__ float2 up2(ull v) {
    float2 f; asm("mov.b64 {%0, %1}, %2;" : "=f"(f.x), "=f"(f.y) : "l"(v)); return f;
}
__device__ __forceinline__ float ftanh(float x) {
    float y; asm("tanh.approx.f32 %0, %1;" : "=f"(y) : "f"(x)); return y;
}
__device__ __forceinline__ float fsigm(float x) {
    return fmaf(0.5f, ftanh(0.5f * x), 0.5f);
}

__device__ __forceinline__ void hadd8(float acc[8], uint4 v) {
    const __half2* h = (const __half2*)&v;
    #pragma unroll
    for (int q = 0; q < 4; q++) {
        float2 f = __half22float2(h[q]);
        acc[2 * q]     += f.x;
        acc[2 * q + 1] += f.y;
    }
}

// ---------------------------------------------------------------------------
// xt16 = fp16( x @ W_gcn ) via HMMA (R13 body). Block 0 also runs the
// int64/int32 edge-index probe (needed before k_scatter).
// ---------------------------------------------------------------------------
__global__ __launch_bounds__(256) void k_gemm_xt(const float* __restrict__ x,
                                                 const float* __restrict__ W,
                                                 const unsigned int* __restrict__ ep,
                                                 int N) {
    extern __shared__ char smb[];
    __half* sA = (__half*)smb;             // [128][136]
    __half* sB = (__half*)(smb + 34816);   // [128][72]
    float*  sC = (float*)smb;              // aliased [128][68]

    const int tid  = threadIdx.x;
    const int base = blockIdx.x * 128;

    if (blockIdx.x == 0 && tid == 0) {
        int is64 = 1;
        for (int i = 0; i < 64; i++)
            if (ep[2 * i + 1] != 0u) { is64 = 0; break; }
        g_is64 = is64;
    }

    for (int i = tid; i < 128 * 32; i += 256) {
        int r = i >> 5, q = i & 31;
        int n = base + r;
        float4 v = make_float4(0.f, 0.f, 0.f, 0.f);
        if (n < N) v = *(const float4*)&x[(long)n * F_IN + q * 4];
        uint2 pk;
        __half2* ph = (__half2*)&pk;
        ph[0] = __float22half2_rn(make_float2(v.x, v.y));
        ph[1] = __float22half2_rn(make_float2(v.z, v.w));
        *(uint2*)&sA[r * 136 + q * 4] = pk;
    }
    for (int i = tid; i < 128 * 16; i += 256) {
        int k = i >> 4, q = i & 15;
        float4 v = *(const float4*)&W[k * H_DIM + q * 4];
        uint2 pk;
        __half2* ph = (__half2*)&pk;
        ph[0] = __float22half2_rn(make_float2(v.x, v.y));
        ph[1] = __float22half2_rn(make_float2(v.z, v.w));
        *(uint2*)&sB[k * 72 + q * 4] = pk;
    }
    __syncthreads();

    const int w = tid >> 5;
    wmma::fragment<wmma::accumulator, 16, 16, 16, float> acc[4];
    #pragma unroll
    for (int ct = 0; ct < 4; ct++) wmma::fill_fragment(acc[ct], 0.0f);

    #pragma unroll
    for (int kk = 0; kk < 8; kk++) {
        wmma::fragment<wmma::matrix_a, 16, 16, 16, __half, wmma::row_major> fa;
        wmma::load_matrix_sync(fa, sA + w * 16 * 136 + kk * 16, 136);
        #pragma unroll
        for (int ct = 0; ct < 4; ct++) {
            wmma::fragment<wmma::matrix_b, 16, 16, 16, __half, wmma::row_major> fb;
            wmma::load_matrix_sync(fb, sB + kk * 16 * 72 + ct * 16, 72);
            wmma::mma_sync(acc[ct], fa, fb, acc[ct]);
        }
    }
    __syncthreads();

    #pragma unroll
    for (int ct = 0; ct < 4; ct++)
        wmma::store_matrix_sync(sC + w * 16 * 68 + ct * 16, acc[ct], 68,
                                wmma::mem_row_major);
    __syncthreads();

    for (int i = tid; i < 128 * 16; i += 256) {
        int r = i >> 4, q = i & 15;
        int n = base + r;
        if (n < N) {
            float4 v = *(const float4*)&sC[r * 68 + q * 4];
            uint2 pk;
            __half2* ph = (__half2*)&pk;
            ph[0] = __float22half2_rn(make_float2(v.x, v.y));
            ph[1] = __float22half2_rn(make_float2(v.z, v.w));
            *(uint2*)&g_xth[(long)n * H_DIM + q * 4] = pk;
        }
    }
}

// ---------------------------------------------------------------------------
// Counting-sort scatter (R13 body).
// ---------------------------------------------------------------------------
__global__ __launch_bounds__(256) void k_scatter(const void* __restrict__ eidx, int E) {
    int i0 = (blockIdx.x * 256 + threadIdx.x) * 4;
    if (i0 >= E) return;
    int m = E - i0; if (m > 4) m = 4;

    int row[4], col[4];
    if (g_is64) {
        const longlong2* pr = (const longlong2*)((const long long*)eidx + i0);
        const long long* pcs = (const long long*)eidx + E + i0;
        if (m == 4 && (((size_t)pcs) & 15) == 0) {
            longlong2 r01 = pr[0], r23 = pr[1];
            longlong2 c01 = ((const longlong2*)pcs)[0], c23 = ((const longlong2*)pcs)[1];
            row[0] = (int)r01.x; row[1] = (int)r01.y; row[2] = (int)r23.x; row[3] = (int)r23.y;
            col[0] = (int)c01.x; col[1] = (int)c01.y; col[2] = (int)c23.x; col[3] = (int)c23.y;
        } else {
            const long long* p = (const long long*)eidx;
            #pragma unroll
            for (int q = 0; q < 4; q++)
                if (q < m) { row[q] = (int)p[i0 + q]; col[q] = (int)p[(long)E + i0 + q]; }
        }
    } else {
        const int* p = (const int*)eidx;
        if (m == 4 && ((E + i0) & 3) == 0) {
            int4 r4 = *(const int4*)&p[i0];
            int4 c4 = *(const int4*)&p[E + i0];
            row[0] = r4.x; row[1] = r4.y; row[2] = r4.z; row[3] = r4.w;
            col[0] = c4.x; col[1] = c4.y; col[2] = c4.z; col[3] = c4.w;
        } else {
            #pragma unroll
            for (int q = 0; q < 4; q++)
                if (q < m) { row[q] = p[i0 + q]; col[q] = p[E + i0 + q]; }
        }
    }
    int pos[4];
    #pragma unroll
    for (int q = 0; q < 4; q++)
        if (q < m) pos[q] = atomicAdd(&g_cur[col[q]], 1);
    #pragma unroll
    for (int q = 0; q < 4; q++)
        if (q < m && pos[q] < CAP) g_src[(long)col[q] * CAP + pos[q]] = row[q];
}

// ---------------------------------------------------------------------------
// Prescale + dis: d = rsqrt(deg+1); g_dis[n] = d; g_xth[n] *= d.
// One uint4 = 8 halves per thread (8 threads/node).
// ---------------------------------------------------------------------------
__global__ __launch_bounds__(256) void k_scale(int N) {
    long i = (long)blockIdx.x * 256 + threadIdx.x;
    if (i >= (long)N * 8) return;
    int n = (int)(i >> 3);
    float d = rsqrtf((float)(g_cur[n] + 1));
    if ((i & 7) == 0) g_dis[n] = d;
    uint4 v = *(const uint4*)&g_xth[i * 8];
    __half2* h = (__half2*)&v;
    #pragma unroll
    for (int q = 0; q < 4; q++) {
        float2 f = __half22float2(h[q]);
        h[q] = __float22half2_rn(make_float2(f.x * d, f.y * d));
    }
    *(uint4*)&g_xth[i * 8] = v;
}

// ---------------------------------------------------------------------------
// Gather (R13 body): 8 threads/node, 16B each, 4-wide loop.
// ---------------------------------------------------------------------------
__global__ __launch_bounds__(256) void k_gather(float* __restrict__ out, int N) {
    const int tid = threadIdx.x;
    const int nl  = tid >> 3, c = tid & 7;
    const int n   = blockIdx.x * 32 + nl;
    if (n >= N) return;

    int cnt = g_cur[n];
    if (cnt > CAP) cnt = CAP;
    const long b = (long)n * CAP;
    const long co = (long)c * 8;

    float acc[8] = {0.f};
    hadd8(acc, __ldcg((const uint4*)&g_xth[(long)n * H_DIM + co]));  // self loop

    int e = 0;
    for (; e + 4 <= cnt; e += 4) {
        int4 s = *(const int4*)&g_src[b + e];
        uint4 v0 = __ldcg((const uint4*)&g_xth[(long)s.x * H_DIM + co]);
        uint4 v1 = __ldcg((const uint4*)&g_xth[(long)s.y * H_DIM + co]);
        uint4 v2 = __ldcg((const uint4*)&g_xth[(long)s.z * H_DIM + co]);
        uint4 v3 = __ldcg((const uint4*)&g_xth[(long)s.w * H_DIM + co]);
        hadd8(acc, v0); hadd8(acc, v1); hadd8(acc, v2); hadd8(acc, v3);
    }
    for (; e < cnt; e++) {
        int r = g_src[b + e];
        hadd8(acc, __ldcg((const uint4*)&g_xth[(long)r * H_DIM + co]));
    }

    const float dn = g_dis[n];
    float4 o0 = make_float4(acc[0] * dn, acc[1] * dn, acc[2] * dn, acc[3] * dn);
    float4 o1 = make_float4(acc[4] * dn, acc[5] * dn, acc[6] * dn, acc[7] * dn);
    *(float4*)&out[(long)n * H_DIM + co]     = o0;
    *(float4*)&out[(long)n * H_DIM + co + 4] = o1;
}

// ---------------------------------------------------------------------------
// Fused GRU (R13/R9 body) + epilogue: re-zero g_cur for the next replay.
// ---------------------------------------------------------------------------
__global__ __launch_bounds__(256, 1) void k_gru(float* __restrict__ out,
                                                const float* __restrict__ h0,
                                                const float* __restrict__ Wih,
                                                const float* __restrict__ Whh,
                                                const float* __restrict__ bih,
                                                const float* __restrict__ bhh,
                                                const float* __restrict__ bg,
                                                int N, int NH, int dup) {
    extern __shared__ float sm[];
    float* gs = sm;                    // 64*132
    float* hs = gs + 64 * 132;
    float* wi = hs + 64 * 132;         // 64*196
    float* wh = wi + 64 * 196;

    const int tid  = threadIdx.x;
    const int base = blockIdx.x * 128;

    for (int i = tid; i < 128 * 64; i += 256) {
        int nl = i >> 6, c = i & 63;
        int n = base + nl;
        float gv = 0.0f, hv = 0.0f;
        if (n < N) {
            gv = out[(long)n * H_DIM + c] + bg[c];
            gv = fmaxf(gv, 0.0f);
            hv = h0[(long)n * H_DIM + c];
        }
        gs[c * 132 + nl] = gv;
        hs[c * 132 + nl] = hv;
    }
    for (int i = tid; i < 192 * 64; i += 256) {
        int j = i >> 6, k = i & 63;
        wi[k * 196 + j] = Wih[i];
        wh[k * 196 + j] = Whh[i];
    }
    // re-zero degree counters for the next graph replay
    if (tid < 128) {
        int n = base + tid;
        if (n < N) g_cur[n] = 0;
    }
    __syncthreads();

    const int ty = tid >> 4, tx = tid & 15;
    const int r0 = ty * 8, c0 = tx * 4;
    const ull z0 = pk2(0.0f);

    float rv[8][4], zv[8][4];

    // ---- pass 1: gates r and z ----
    {
        ull R[4][4], Z[4][4];
        #pragma unroll
        for (int ip = 0; ip < 4; ip++)
            #pragma unroll
            for (int j = 0; j < 4; j++) { R[ip][j] = z0; Z[ip][j] = z0; }

        #pragma unroll 2
        for (int k = 0; k < H_DIM; k++) {
            ulonglong2 a01 = *(const ulonglong2*)&gs[k * 132 + r0];
            ulonglong2 a23 = *(const ulonglong2*)&gs[k * 132 + r0 + 4];
            ulonglong2 h01 = *(const ulonglong2*)&hs[k * 132 + r0];
            ulonglong2 h23 = *(const ulonglong2*)&hs[k * 132 + r0 + 4];
            ull ap[4] = {a01.x, a01.y, a23.x, a23.y};
            ull hp[4] = {h01.x, h01.y, h23.x, h23.y};

            float4 ur = *(const float4*)&wi[k * 196 + c0];
            float4 vr = *(const float4*)&wh[k * 196 + c0];
            float4 uz = *(const float4*)&wi[k * 196 + 64 + c0];
            float4 vz = *(const float4*)&wh[k * 196 + 64 + c0];
            ull urb[4] = {pk2(ur.x), pk2(ur.y), pk2(ur.z), pk2(ur.w)};
            ull vrb[4] = {pk2(vr.x), pk2(vr.y), pk2(vr.z), pk2(vr.w)};
            ull uzb[4] = {pk2(uz.x), pk2(uz.y), pk2(uz.z), pk2(uz.w)};
            ull vzb[4] = {pk2(vz.x), pk2(vz.y), pk2(vz.z), pk2(vz.w)};

            #pragma unroll
            for (int ip = 0; ip < 4; ip++)
                #pragma unroll
                for (int j = 0; j < 4; j++) {
                    fma2(R[ip][j], ap[ip], urb[j]);
                    fma2(R[ip][j], hp[ip], vrb[j]);
                    fma2(Z[ip][j], ap[ip], uzb[j]);
                    fma2(Z[ip][j], hp[ip], vzb[j]);
                }
        }

        float4 b1r = *(const float4*)&bih[c0];
        float4 b2r = *(const float4*)&bhh[c0];
        float4 b1z = *(const float4*)&bih[64 + c0];
        float4 b2z = *(const float4*)&bhh[64 + c0];
        float br[4] = {b1r.x + b2r.x, b1r.y + b2r.y, b1r.z + b2r.z, b1r.w + b2r.w};
        float bz[4] = {b1z.x + b2z.x, b1z.y + b2z.y, b1z.z + b2z.z, b1z.w + b2z.w};

        #pragma unroll
        for (int ip = 0; ip < 4; ip++)
            #pragma unroll
            for (int j = 0; j < 4; j++) {
                float2 rr = up2(R[ip][j]);
                float2 zz = up2(Z[ip][j]);
                rv[2 * ip][j]     = fsigm(rr.x + br[j]);
                rv[2 * ip + 1][j] = fsigm(rr.y + br[j]);
                zv[2 * ip][j]     = fsigm(zz.x + bz[j]);
                zv[2 * ip + 1][j] = fsigm(zz.y + bz[j]);
            }
    }

    // ---- pass 2: gate n + output ----
    {
        ull NA[4][4], NB[4][4];
        #pragma unroll
        for (int ip = 0; ip < 4; ip++)
            #pragma unroll
            for (int j = 0; j < 4; j++) { NA[ip][j] = z0; NB[ip][j] = z0; }

        #pragma unroll 2
        for (int k = 0; k < H_DIM; k++) {
            ulonglong2 a01 = *(const ulonglong2*)&gs[k * 132 + r0];
            ulonglong2 a23 = *(const ulonglong2*)&gs[k * 132 + r0 + 4];
            ulonglong2 h01 = *(const ulonglong2*)&hs[k * 132 + r0];
            ulonglong2 h23 = *(const ulonglong2*)&hs[k * 132 + r0 + 4];
            ull ap[4] = {a01.x, a01.y, a23.x, a23.y};
            ull hp[4] = {h01.x, h01.y, h23.x, h23.y};

            float4 un = *(const float4*)&wi[k * 196 + 128 + c0];
            float4 vn = *(const float4*)&wh[k * 196 + 128 + c0];
            ull unb[4] = {pk2(un.x), pk2(un.y), pk2(un.z), pk2(un.w)};
            ull vnb[4] = {pk2(vn.x), pk2(vn.y), pk2(vn.z), pk2(vn.w)};

            #pragma unroll
            for (int ip = 0; ip < 4; ip++)
                #pragma unroll
                for (int j = 0; j < 4; j++) {
                    fma2(NA[ip][j], ap[ip], unb[j]);
                    fma2(NB[ip][j], hp[ip], vnb[j]);
                }
        }

        float4 b1n = *(const float4*)&bih[128 + c0];
        float4 b2n = *(const float4*)&bhh[128 + c0];
        float bi[4] = {b1n.x, b1n.y, b1n.z, b1n.w};
        float bh[4] = {b2n.x, b2n.y, b2n.z, b2n.w};

        float ov[8][4];
        #pragma unroll
        for (int ip = 0; ip < 4; ip++)
            #pragma unroll
            for (int j = 0; j < 4; j++) {
                float2 na = up2(NA[ip][j]);
                float2 nb = up2(NB[ip][j]);
                float2 hv = *(const float2*)&hs[(c0 + j) * 132 + r0 + 2 * ip];
                int i0 = 2 * ip;
                float n0f = ftanh(na.x + bi[j] + rv[i0][j] * (nb.x + bh[j]));
                float n1f = ftanh(na.y + bi[j] + rv[i0 + 1][j] * (nb.y + bh[j]));
                ov[i0][j]     = (1.0f - zv[i0][j]) * n0f + zv[i0][j] * hv.x;
                ov[i0 + 1][j] = (1.0f - zv[i0 + 1][j]) * n1f + zv[i0 + 1][j] * hv.y;
            }

        #pragma unroll
        for (int i = 0; i < 8; i++) {
            int n = base + r0 + i;
            if (n < N) {
                float4 o = make_float4(ov[i][0], ov[i][1], ov[i][2], ov[i][3]);
                *(float4*)&out[(long)n * H_DIM + c0] = o;
                if (dup) *(float4*)&out[(long)NH + (long)n * H_DIM + c0] = o;
            }
        }
    }
}

// ---------------------------------------------------------------------------
extern "C" void kernel_launch(void* const* d_in, const int* in_sizes, int n_in,
                              void* d_out, int out_size) {
    const float* x    = (const float*)d_in[0];
    const void*  eidx = d_in[1];
    const float* h0   = (const float*)d_in[2];
    const float* Wg   = (const float*)d_in[3];
    const float* bg   = (const float*)d_in[4];
    const float* Wih  = (const float*)d_in[5];
    const float* Whh  = (const float*)d_in[6];
    const float* bih  = (const float*)d_in[7];
    const float* bhh  = (const float*)d_in[8];
    float* out = (float*)d_out;

    const int  N  = in_sizes[0] / F_IN;
    const int  E  = in_sizes[1] / 2;
    const long NH = (long)N * H_DIM;
    const int  dup = (out_size >= 2 * NH) ? 1 : 0;

    const int gemm_smem = 53248;
    cudaFuncSetAttribute(k_gemm_xt, cudaFuncAttributeMaxDynamicSharedMemorySize, gemm_smem);
    k_gemm_xt<<<(N + 127) / 128, 256, gemm_smem>>>(x, Wg, (const unsigned int*)eidx, N);

    k_scatter<<<(E / 4 + 255) / 256, 256>>>(eidx, E);
    k_scale<<<(int)(((long)N * 8 + 255) / 256), 256>>>(N);
    k_gather<<<(N + 31) / 32, 256>>>(out, N);

    const int gru_smem = (2 * 64 * 132 + 2 * 64 * 196) * (int)sizeof(float);
    cudaFuncSetAttribute(k_gru, cudaFuncAttributeMaxDynamicSharedMemorySize, gru_smem);
    k_gru<<<(N + 127) / 128, 256, gru_smem>>>(out, h0, Wih, Whh, bih, bhh, bg,
                                              N, (int)NH, dup);
}